// round 9
// baseline (speedup 1.0000x reference)
#include <cuda_runtime.h>
#include <math.h>

// ---------------------------------------------------------------------------
// OwlViT prediction head
//   B=32, P=576, DV=768, DT=512, N_PARTS=12, K=3, NUM_CLASSES=800
//   out = [logits_reshaped (384*9600) | pred_logits (32*800)] fp32
// ---------------------------------------------------------------------------

#define Bsz 32
#define Pn 576
#define DV 768
#define DT 512
#define NPART 12
#define TOPK 3
#define NCLS 800
#define NQ (NCLS * NPART)      // 9600 query rows per batch
#define MROWS (Bsz * NPART)    // 384
#define LOGITS_ELEMS ((size_t)MROWS * NQ)

// scratch (static device memory; no allocations allowed)
__device__ float g_h1[MROWS * DV];
__device__ float g_h2[MROWS * DV];
__device__ float g_img[MROWS * DT];

// ---------------------------------------------------------------------------
__device__ __forceinline__ void fma2(unsigned long long& d,
                                     unsigned long long a,
                                     unsigned long long b) {
    asm("fma.rn.f32x2 %0, %1, %2, %0;" : "+l"(d) : "l"(a), "l"(b));
}

__device__ __forceinline__ float pair_sum(unsigned long long v) {
    float lo = __uint_as_float((unsigned)(v & 0xffffffffull));
    float hi = __uint_as_float((unsigned)(v >> 32));
    return lo + hi;
}

__device__ __forceinline__ float gelu_exact(float x) {
    return 0.5f * x * (1.0f + erff(x * 0.70710678118654752f));
}

// ---------------------------------------------------------------------------
// GEMM: C[M,N] = gelu(A[M,768] * W[N,768]^T + bias), smem double-buffered.
// BM=32 BN=64 BK=32, 256 threads, 2x4 outputs/thread, f32x2 k-pair FMAs.
// GATHER=true: A row r is the dedup-sum of topk image rows (fused gather).
// ---------------------------------------------------------------------------
#define GBM 32
#define GBN 64
#define GBK 32
#define GPAD 36
#define NITER (DV / GBK)   // 24

template<bool GATHER>
__global__ void __launch_bounds__(256)
gemm_kernel(const float* __restrict__ A, const float* __restrict__ W,
            const float* __restrict__ bias, float* __restrict__ C, int N,
            const int* __restrict__ idx) {
    __shared__ __align__(16) float As[2][GBM][GPAD];
    __shared__ __align__(16) float Ws[2][GBN][GPAD];
    int t = threadIdx.x;
    int tx = t & 15;                 // cols tx + 16j
    int ty = t >> 4;                 // rows ty*2 + i
    int bm = blockIdx.x * GBM, bn = blockIdx.y * GBN;

    int ar = t >> 3, ak = (t & 7) * 4;    // A tile: 1 float4/thread
    int wr = t >> 2, wk = (t & 3) * 8;    // W tile: 2 float4/thread

    const float *Arow0, *Arow1, *Arow2;
    bool u1 = false, u2 = false;
    if (GATHER) {
        int row = bm + ar;
        int bb = row / NPART, n = row - bb * NPART;
        int i0 = idx[(bb * TOPK + 0) * NPART + n];
        int i1 = idx[(bb * TOPK + 1) * NPART + n];
        int i2 = idx[(bb * TOPK + 2) * NPART + n];
        i0 = min(max(i0, 0), Pn - 1);
        i1 = min(max(i1, 0), Pn - 1);
        i2 = min(max(i2, 0), Pn - 1);
        u1 = (i1 != i0);
        u2 = (i2 != i0) && (i2 != i1);
        const float* base = A + (size_t)bb * Pn * DV;
        Arow0 = base + (size_t)i0 * DV;
        Arow1 = base + (size_t)i1 * DV;
        Arow2 = base + (size_t)i2 * DV;
    } else {
        Arow0 = A + (size_t)(bm + ar) * DV;
        Arow1 = Arow0; Arow2 = Arow0;
    }
    const float* Wg = W + (size_t)(bn + wr) * DV;

    auto loadA = [&](int k0) -> float4 {
        float4 s = *(const float4*)(Arow0 + k0 + ak);
        if (GATHER) {
            if (u1) { float4 v = *(const float4*)(Arow1 + k0 + ak);
                      s.x += v.x; s.y += v.y; s.z += v.z; s.w += v.w; }
            if (u2) { float4 v = *(const float4*)(Arow2 + k0 + ak);
                      s.x += v.x; s.y += v.y; s.z += v.z; s.w += v.w; }
        }
        return s;
    };

    unsigned long long acc2[2][4];
#pragma unroll
    for (int i = 0; i < 2; ++i)
#pragma unroll
        for (int j = 0; j < 4; ++j) acc2[i][j] = 0ull;

    // prologue: tile0 -> smem[0]; tile1 -> regs
    float4 a_r = loadA(0);
    float4 w_r0 = *(const float4*)(Wg + wk);
    float4 w_r1 = *(const float4*)(Wg + wk + 4);
    *(float4*)&As[0][ar][ak] = a_r;
    *(float4*)&Ws[0][wr][wk] = w_r0;
    *(float4*)&Ws[0][wr][wk + 4] = w_r1;
    a_r  = loadA(GBK);
    w_r0 = *(const float4*)(Wg + GBK + wk);
    w_r1 = *(const float4*)(Wg + GBK + wk + 4);
    __syncthreads();

#pragma unroll 1
    for (int i = 0; i < NITER; ++i) {
        int buf = i & 1, nbuf = buf ^ 1;
        if (i + 1 < NITER) {
            *(float4*)&As[nbuf][ar][ak] = a_r;
            *(float4*)&Ws[nbuf][wr][wk] = w_r0;
            *(float4*)&Ws[nbuf][wr][wk + 4] = w_r1;
        }
        if (i + 2 < NITER) {
            int k0 = (i + 2) * GBK;
            a_r  = loadA(k0);
            w_r0 = *(const float4*)(Wg + k0 + wk);
            w_r1 = *(const float4*)(Wg + k0 + wk + 4);
        }
#pragma unroll
        for (int kk = 0; kk < GBK; kk += 4) {
            ulonglong2 ap[2], wp[4];
            ap[0] = *(const ulonglong2*)&As[buf][ty * 2][kk];
            ap[1] = *(const ulonglong2*)&As[buf][ty * 2 + 1][kk];
#pragma unroll
            for (int j = 0; j < 4; ++j)
                wp[j] = *(const ulonglong2*)&Ws[buf][tx + 16 * j][kk];
#pragma unroll
            for (int ii = 0; ii < 2; ++ii)
#pragma unroll
                for (int j = 0; j < 4; ++j) {
                    fma2(acc2[ii][j], ap[ii].x, wp[j].x);
                    fma2(acc2[ii][j], ap[ii].y, wp[j].y);
                }
        }
        __syncthreads();
    }

#pragma unroll
    for (int i = 0; i < 2; ++i) {
        int row = bm + ty * 2 + i;
#pragma unroll
        for (int j = 0; j < 4; ++j) {
            int col = bn + tx + 16 * j;
            float x = pair_sum(acc2[i][j]) + bias[col];
            C[(size_t)row * N + col] = gelu_exact(x);
        }
    }
}

// ---------------------------------------------------------------------------
// logits: lane-owns-row, 2 rows per thread, reg-prefetch double buffering.
// Block = 192 threads owning rows {t, t+192} of a 384-row stripe.
// q tiles: 384 rows x 8 k, slot-major smem [buf][slot][row] float4 ->
// STS and LDS phases are runs of 32 consecutive float4 (conflict-free,
// no rotation). img reads are warp-uniform broadcasts amortized over 2
// rows. One __syncthreads per tile (R6-proven pipeline).
// Dynamic smem: q 2x12KB + img 24KB = 48KB -> 3 blocks/SM (18 warps).
// ---------------------------------------------------------------------------
#define QT 8
#define NT (DT / QT)     // 64 tiles
#define RPT 2
#define TPB 192
#define RPB 384          // rows per block; grid.x = 9600/384 = 25

__global__ void __launch_bounds__(TPB, 3)
logits_kernel(const float* __restrict__ q, float* __restrict__ out) {
    extern __shared__ __align__(16) float smem[];
    float4* q_s  = (float4*)smem;          // [2][2][384] float4 = 24KB
    float* img_s = smem + 6144;            // 12*512 floats = 24KB

    int t = threadIdx.x;
    int warp = t >> 5, lane = t & 31;
    int b = blockIdx.y;

    const float* qb = q + (size_t)b * NQ * DT + (size_t)(blockIdx.x * RPB) * DT;

    // staging map: idx = j*192 + t (j<4) -> slot = idx/384, row = idx%384
    float4 pf[4];
    auto ldgTile = [&](int tile) {
#pragma unroll
        for (int j = 0; j < 4; ++j) {
            int idx = j * TPB + t;
            int slot = idx >= RPB, row = idx - slot * RPB;
            pf[j] = *(const float4*)(qb + (size_t)row * DT + tile * QT + slot * 4);
        }
    };
    auto stsTile = [&](int buf) {
#pragma unroll
        for (int j = 0; j < 4; ++j) {
            int idx = j * TPB + t;
            int slot = idx >= RPB, row = idx - slot * RPB;
            q_s[(buf * 2 + slot) * RPB + row] = pf[j];
        }
    };

    {   // stage img tile for this batch (1536 float4, 8/thread)
        const float4* src = (const float4*)(g_img + (size_t)b * NPART * DT);
        float4* dst = (float4*)img_s;
#pragma unroll
        for (int i = 0; i < 8; ++i)
            dst[t + i * TPB] = src[t + i * TPB];
    }
    __syncthreads();

    // fused l2 normalization of the 12 img rows (6 warps, 2 rows each)
    for (int row = warp; row < NPART; row += 6) {
        float* rp = img_s + row * DT;
        float4 v0 = *(float4*)(rp + lane * 4);
        float4 v1 = *(float4*)(rp + lane * 4 + 128);
        float4 v2 = *(float4*)(rp + lane * 4 + 256);
        float4 v3 = *(float4*)(rp + lane * 4 + 384);
        float ss = v0.x*v0.x + v0.y*v0.y + v0.z*v0.z + v0.w*v0.w
                 + v1.x*v1.x + v1.y*v1.y + v1.z*v1.z + v1.w*v1.w
                 + v2.x*v2.x + v2.y*v2.y + v2.z*v2.z + v2.w*v2.w
                 + v3.x*v3.x + v3.y*v3.y + v3.z*v3.z + v3.w*v3.w;
#pragma unroll
        for (int off = 16; off > 0; off >>= 1)
            ss += __shfl_xor_sync(0xffffffffu, ss, off);
        float rinv = 1.0f / fmaxf(sqrtf(ss), 1e-12f);
        v0.x*=rinv; v0.y*=rinv; v0.z*=rinv; v0.w*=rinv;
        v1.x*=rinv; v1.y*=rinv; v1.z*=rinv; v1.w*=rinv;
        v2.x*=rinv; v2.y*=rinv; v2.z*=rinv; v2.w*=rinv;
        v3.x*=rinv; v3.y*=rinv; v3.z*=rinv; v3.w*=rinv;
        *(float4*)(rp + lane * 4)       = v0;
        *(float4*)(rp + lane * 4 + 128) = v1;
        *(float4*)(rp + lane * 4 + 256) = v2;
        *(float4*)(rp + lane * 4 + 384) = v3;
    }

    unsigned long long acc[RPT][13];
#pragma unroll
    for (int r = 0; r < RPT; ++r)
#pragma unroll
        for (int j = 0; j < 13; ++j) acc[r][j] = 0ull;

    // prologue: tile0 -> smem buf0; tile1 -> regs
    ldgTile(0);
    stsTile(0);
    ldgTile(1);
    __syncthreads();

#pragma unroll 1
    for (int tile = 0; tile < NT; ++tile) {
        int buf = tile & 1;
        if (tile + 1 < NT) stsTile(buf ^ 1);
        if (tile + 2 < NT) ldgTile(tile + 2);
#pragma unroll
        for (int c = 0; c < 2; ++c) {
            int k = tile * QT + c * 4;
            ulonglong2 qp[RPT];
#pragma unroll
            for (int r = 0; r < RPT; ++r)
                qp[r] = *(const ulonglong2*)&q_s[(buf * 2 + c) * RPB + t + TPB * r];
#pragma unroll
            for (int n = 0; n < NPART; ++n) {
                ulonglong2 im = *(const ulonglong2*)&img_s[n * DT + k];
#pragma unroll
                for (int r = 0; r < RPT; ++r) {
                    fma2(acc[r][n], qp[r].x, im.x);
                    fma2(acc[r][n], qp[r].y, im.y);
                }
            }
#pragma unroll
            for (int r = 0; r < RPT; ++r) {
                fma2(acc[r][12], qp[r].x, qp[r].x);
                fma2(acc[r][12], qp[r].y, qp[r].y);
            }
        }
        __syncthreads();
    }

#pragma unroll
    for (int r = 0; r < RPT; ++r) {
        float s[13];
#pragma unroll
        for (int j = 0; j < 13; ++j) s[j] = pair_sum(acc[r][j]);
        float rinv = 1.0f / fmaxf(sqrtf(s[12]), 1e-12f);
        int gr = blockIdx.x * RPB + t + TPB * r;
#pragma unroll
        for (int n = 0; n < NPART; ++n)
            out[((size_t)(b * NPART + n)) * NQ + gr] = s[n] * rinv;
    }
}

// ---------------------------------------------------------------------------
// pred_logits[b,c] = sum_n logits[b,n,c*12+n]
// ---------------------------------------------------------------------------
__global__ void pred_kernel(float* __restrict__ out) {
    int t = blockIdx.x * blockDim.x + threadIdx.x;   // 0..25599
    if (t >= Bsz * NCLS) return;
    int b = t / NCLS, c = t % NCLS;
    float s = 0.0f;
#pragma unroll
    for (int n = 0; n < NPART; ++n)
        s += out[((size_t)(b * NPART + n)) * NQ + c * NPART + n];
    out[LOGITS_ELEMS + t] = s;
}

// ---------------------------------------------------------------------------
extern "C" void kernel_launch(void* const* d_in, const int* in_sizes, int n_in,
                              void* d_out, int out_size) {
    const float* image = (const float*)d_in[0];
    const float* query = (const float*)d_in[1];
    const int* topk = (const int*)d_in[2];
    const float* W1 = (const float*)d_in[3];
    const float* b1 = (const float*)d_in[4];
    const float* W2 = (const float*)d_in[5];
    const float* b2 = (const float*)d_in[6];
    const float* W3 = (const float*)d_in[7];
    const float* b3 = (const float*)d_in[8];
    float* out = (float*)d_out;

    float* h1; float* h2; float* img;
    cudaGetSymbolAddress((void**)&h1, g_h1);
    cudaGetSymbolAddress((void**)&h2, g_h2);
    cudaGetSymbolAddress((void**)&img, g_img);

    const int LOGITS_SMEM = 49152;   // 24KB q (2 buf) + 24KB img
    cudaFuncSetAttribute(logits_kernel,
                         cudaFuncAttributeMaxDynamicSharedMemorySize,
                         LOGITS_SMEM);

    // launch order keeps logits at global index 5 (2 harness preamble
    // launches + 3 here) so ncu -s 5 -c 1 captures it.
    gemm_kernel<true ><<<dim3(MROWS / GBM, DV / GBN), 256>>>(image, W1, b1, h1, DV, topk);
    gemm_kernel<false><<<dim3(MROWS / GBM, DV / GBN), 256>>>(h1, W2, b2, h2, DV, nullptr);
    gemm_kernel<false><<<dim3(MROWS / GBM, DT / GBN), 256>>>(h2, W3, b3, img, DT, nullptr);
    logits_kernel<<<dim3(NQ / RPB, Bsz), TPB, LOGITS_SMEM>>>(query, out);
    pred_kernel<<<(Bsz * NCLS + 255) / 256, 256>>>(out);
}

// round 11
// speedup vs baseline: 1.2377x; 1.2377x over previous
#include <cuda_runtime.h>
#include <math.h>

// ---------------------------------------------------------------------------
// OwlViT prediction head
//   B=32, P=576, DV=768, DT=512, N_PARTS=12, K=3, NUM_CLASSES=800
//   out = [logits_reshaped (384*9600) | pred_logits (32*800)] fp32
// ---------------------------------------------------------------------------

#define Bsz 32
#define Pn 576
#define DV 768
#define DT 512
#define NPART 12
#define TOPK 3
#define NCLS 800
#define NQ (NCLS * NPART)      // 9600 query rows per batch
#define MROWS (Bsz * NPART)    // 384
#define LOGITS_ELEMS ((size_t)MROWS * NQ)

// scratch (static device memory; no allocations allowed)
__device__ float g_h1[MROWS * DV];
__device__ float g_h2[MROWS * DV];
__device__ float g_img[MROWS * DT];

// ---------------------------------------------------------------------------
__device__ __forceinline__ void fma2(unsigned long long& d,
                                     unsigned long long a,
                                     unsigned long long b) {
    asm("fma.rn.f32x2 %0, %1, %2, %0;" : "+l"(d) : "l"(a), "l"(b));
}

__device__ __forceinline__ float pair_sum(unsigned long long v) {
    float lo = __uint_as_float((unsigned)(v & 0xffffffffull));
    float hi = __uint_as_float((unsigned)(v >> 32));
    return lo + hi;
}

__device__ __forceinline__ float gelu_exact(float x) {
    return 0.5f * x * (1.0f + erff(x * 0.70710678118654752f));
}

__device__ __forceinline__ void cp_async16(unsigned dst, const void* src) {
    asm volatile("cp.async.cg.shared.global [%0], [%1], 16;"
                 :: "r"(dst), "l"(src));
}
__device__ __forceinline__ void cp_commit() {
    asm volatile("cp.async.commit_group;");
}
__device__ __forceinline__ void cp_wait1() {
    asm volatile("cp.async.wait_group 1;");
}
__device__ __forceinline__ void cp_wait0() {
    asm volatile("cp.async.wait_group 0;");
}

// ---------------------------------------------------------------------------
// GEMM: C[M,N] = gelu(A[M,768] * W[N,768]^T + bias), smem double-buffered.
// BM=32 BN=64 BK=32, 256 threads, 2x4 outputs/thread, f32x2 k-pair FMAs.
// GATHER=true: A row r is the dedup-sum of topk image rows (fused gather).
// ---------------------------------------------------------------------------
#define GBM 32
#define GBN 64
#define GBK 32
#define GPAD 36
#define NITER (DV / GBK)   // 24

template<bool GATHER>
__global__ void __launch_bounds__(256)
gemm_kernel(const float* __restrict__ A, const float* __restrict__ W,
            const float* __restrict__ bias, float* __restrict__ C, int N,
            const int* __restrict__ idx) {
    __shared__ __align__(16) float As[2][GBM][GPAD];
    __shared__ __align__(16) float Ws[2][GBN][GPAD];
    int t = threadIdx.x;
    int tx = t & 15;                 // cols tx + 16j
    int ty = t >> 4;                 // rows ty*2 + i
    int bm = blockIdx.x * GBM, bn = blockIdx.y * GBN;

    int ar = t >> 3, ak = (t & 7) * 4;    // A tile: 1 float4/thread
    int wr = t >> 2, wk = (t & 3) * 8;    // W tile: 2 float4/thread

    const float *Arow0, *Arow1, *Arow2;
    bool u1 = false, u2 = false;
    if (GATHER) {
        int row = bm + ar;
        int bb = row / NPART, n = row - bb * NPART;
        int i0 = idx[(bb * TOPK + 0) * NPART + n];
        int i1 = idx[(bb * TOPK + 1) * NPART + n];
        int i2 = idx[(bb * TOPK + 2) * NPART + n];
        i0 = min(max(i0, 0), Pn - 1);
        i1 = min(max(i1, 0), Pn - 1);
        i2 = min(max(i2, 0), Pn - 1);
        u1 = (i1 != i0);
        u2 = (i2 != i0) && (i2 != i1);
        const float* base = A + (size_t)bb * Pn * DV;
        Arow0 = base + (size_t)i0 * DV;
        Arow1 = base + (size_t)i1 * DV;
        Arow2 = base + (size_t)i2 * DV;
    } else {
        Arow0 = A + (size_t)(bm + ar) * DV;
        Arow1 = Arow0; Arow2 = Arow0;
    }
    const float* Wg = W + (size_t)(bn + wr) * DV;

    auto loadA = [&](int k0) -> float4 {
        float4 s = *(const float4*)(Arow0 + k0 + ak);
        if (GATHER) {
            if (u1) { float4 v = *(const float4*)(Arow1 + k0 + ak);
                      s.x += v.x; s.y += v.y; s.z += v.z; s.w += v.w; }
            if (u2) { float4 v = *(const float4*)(Arow2 + k0 + ak);
                      s.x += v.x; s.y += v.y; s.z += v.z; s.w += v.w; }
        }
        return s;
    };

    unsigned long long acc2[2][4];
#pragma unroll
    for (int i = 0; i < 2; ++i)
#pragma unroll
        for (int j = 0; j < 4; ++j) acc2[i][j] = 0ull;

    // prologue: tile0 -> smem[0]; tile1 -> regs
    float4 a_r = loadA(0);
    float4 w_r0 = *(const float4*)(Wg + wk);
    float4 w_r1 = *(const float4*)(Wg + wk + 4);
    *(float4*)&As[0][ar][ak] = a_r;
    *(float4*)&Ws[0][wr][wk] = w_r0;
    *(float4*)&Ws[0][wr][wk + 4] = w_r1;
    a_r  = loadA(GBK);
    w_r0 = *(const float4*)(Wg + GBK + wk);
    w_r1 = *(const float4*)(Wg + GBK + wk + 4);
    __syncthreads();

#pragma unroll 1
    for (int i = 0; i < NITER; ++i) {
        int buf = i & 1, nbuf = buf ^ 1;
        if (i + 1 < NITER) {
            *(float4*)&As[nbuf][ar][ak] = a_r;
            *(float4*)&Ws[nbuf][wr][wk] = w_r0;
            *(float4*)&Ws[nbuf][wr][wk + 4] = w_r1;
        }
        if (i + 2 < NITER) {
            int k0 = (i + 2) * GBK;
            a_r  = loadA(k0);
            w_r0 = *(const float4*)(Wg + k0 + wk);
            w_r1 = *(const float4*)(Wg + k0 + wk + 4);
        }
#pragma unroll
        for (int kk = 0; kk < GBK; kk += 4) {
            ulonglong2 ap[2], wp[4];
            ap[0] = *(const ulonglong2*)&As[buf][ty * 2][kk];
            ap[1] = *(const ulonglong2*)&As[buf][ty * 2 + 1][kk];
#pragma unroll
            for (int j = 0; j < 4; ++j)
                wp[j] = *(const ulonglong2*)&Ws[buf][tx + 16 * j][kk];
#pragma unroll
            for (int ii = 0; ii < 2; ++ii)
#pragma unroll
                for (int j = 0; j < 4; ++j) {
                    fma2(acc2[ii][j], ap[ii].x, wp[j].x);
                    fma2(acc2[ii][j], ap[ii].y, wp[j].y);
                }
        }
        __syncthreads();
    }

#pragma unroll
    for (int i = 0; i < 2; ++i) {
        int row = bm + ty * 2 + i;
#pragma unroll
        for (int j = 0; j < 4; ++j) {
            int col = bn + tx + 16 * j;
            float x = pair_sum(acc2[i][j]) + bias[col];
            C[(size_t)row * N + col] = gelu_exact(x);
        }
    }
}

// ---------------------------------------------------------------------------
// logits: lane-owns-row, 2 rows/thread, cp.async 3-stage pipeline.
// Block = 128 threads owning rows {t, t+128} of a 256-row stripe.
// q tiles 256 rows x 16 k, staged with a 4-lane-per-row LDG footprint into
// slot-major smem [buf][slot][row] float4 with +2-row rotation per slot
// (LDGSTS store phase and LDS read phase both bank-conflict-free).
// One __syncthreads per tile; wait_group(1) normally, wait_group(0) on the
// FINAL tile (only 1 group pending there -> wait_group(1) would not wait:
// that was the R10 correctness bug).
// img broadcasts amortized over 2 rows. acc = 2x13 f32x2 (52 regs), no
// prefetch registers. Dynamic smem: q 3x16KB + img 24KB = 72KB -> 3 blk/SM.
// ---------------------------------------------------------------------------
#define QT 16
#define NT (DT / QT)     // 32 tiles
#define RPT 2
#define TPB 128
#define RPB 256          // grid.x = ceil(9600/256) = 38 (last block guarded)

__global__ void __launch_bounds__(TPB, 3)
logits_kernel(const float* __restrict__ q, float* __restrict__ out) {
    extern __shared__ __align__(16) float smem[];
    float4* q_s  = (float4*)smem;          // [3][4][256] float4 = 48KB
    float* img_s = smem + 12288;           // 12*512 floats = 24KB

    int t = threadIdx.x;
    int warp = t >> 5, lane = t & 31;
    int b = blockIdx.y;
    int r0 = blockIdx.x * RPB;

    const float* qB = q + (size_t)b * NQ * DT;

    // cp.async staging: 8 x 16B per thread per tile.
    // idx = j*128 + t -> row = idx>>2 (4 lanes per row), slot = idx&3.
    // dst smem: plane (buf*4+slot), row rotated by +2*slot (conflict-free).
    auto issueTile = [&](int tile, int buf) {
#pragma unroll
        for (int j = 0; j < 8; ++j) {
            int idx = j * TPB + t;
            int row = idx >> 2, slot = idx & 3;
            int rg = r0 + row; if (rg > NQ - 1) rg = NQ - 1;   // last-block clamp
            int rr = (row + 2 * slot) & (RPB - 1);
            unsigned dst = (unsigned)__cvta_generic_to_shared(
                &q_s[(buf * 4 + slot) * RPB + rr]);
            cp_async16(dst, qB + (size_t)rg * DT + tile * QT + slot * 4);
        }
        cp_commit();
    };

    // start the pipeline before img staging
    issueTile(0, 0);
    issueTile(1, 1);

    {   // stage img tile for this batch (1536 float4, 12/thread)
        const float4* src = (const float4*)(g_img + (size_t)b * NPART * DT);
        float4* dst = (float4*)img_s;
#pragma unroll
        for (int i = 0; i < 12; ++i)
            dst[t + i * TPB] = src[t + i * TPB];
    }
    __syncthreads();

    // fused l2 normalization of the 12 img rows (4 warps, 3 rows each)
    for (int row = warp; row < NPART; row += 4) {
        float* rp = img_s + row * DT;
        float4 v0 = *(float4*)(rp + lane * 4);
        float4 v1 = *(float4*)(rp + lane * 4 + 128);
        float4 v2 = *(float4*)(rp + lane * 4 + 256);
        float4 v3 = *(float4*)(rp + lane * 4 + 384);
        float ss = v0.x*v0.x + v0.y*v0.y + v0.z*v0.z + v0.w*v0.w
                 + v1.x*v1.x + v1.y*v1.y + v1.z*v1.z + v1.w*v1.w
                 + v2.x*v2.x + v2.y*v2.y + v2.z*v2.z + v2.w*v2.w
                 + v3.x*v3.x + v3.y*v3.y + v3.z*v3.z + v3.w*v3.w;
#pragma unroll
        for (int off = 16; off > 0; off >>= 1)
            ss += __shfl_xor_sync(0xffffffffu, ss, off);
        float rinv = 1.0f / fmaxf(sqrtf(ss), 1e-12f);
        v0.x*=rinv; v0.y*=rinv; v0.z*=rinv; v0.w*=rinv;
        v1.x*=rinv; v1.y*=rinv; v1.z*=rinv; v1.w*=rinv;
        v2.x*=rinv; v2.y*=rinv; v2.z*=rinv; v2.w*=rinv;
        v3.x*=rinv; v3.y*=rinv; v3.z*=rinv; v3.w*=rinv;
        *(float4*)(rp + lane * 4)       = v0;
        *(float4*)(rp + lane * 4 + 128) = v1;
        *(float4*)(rp + lane * 4 + 256) = v2;
        *(float4*)(rp + lane * 4 + 384) = v3;
    }
    // img-norm visibility to all warps is covered by the first in-loop
    // __syncthreads below (before any compute reads img_s).

    unsigned long long acc[RPT][13];
#pragma unroll
    for (int r = 0; r < RPT; ++r)
#pragma unroll
        for (int j = 0; j < 13; ++j) acc[r][j] = 0ull;

#pragma unroll 1
    for (int tile = 0; tile < NT; ++tile) {
        int buf = tile % 3;
        // pending groups here: {tile, tile+1} normally -> wait_group(1)
        // drains group 'tile'. On the LAST tile only {tile} is pending, so
        // wait_group(1) would NOT wait -> must drain all (R10 bug fix).
        if (tile + 1 < NT) cp_wait1(); else cp_wait0();
        __syncthreads();             // all threads' copies + img norm visible

#pragma unroll
        for (int c = 0; c < 4; ++c) {
            int k = tile * QT + c * 4;
            ulonglong2 qp[RPT];
#pragma unroll
            for (int r = 0; r < RPT; ++r) {
                int rr = (t + TPB * r + 2 * c) & (RPB - 1);
                qp[r] = *(const ulonglong2*)&q_s[(buf * 4 + c) * RPB + rr];
            }
#pragma unroll
            for (int n = 0; n < NPART; ++n) {
                ulonglong2 im = *(const ulonglong2*)&img_s[n * DT + k];
#pragma unroll
                for (int r = 0; r < RPT; ++r) {
                    fma2(acc[r][n], qp[r].x, im.x);
                    fma2(acc[r][n], qp[r].y, im.y);
                }
            }
#pragma unroll
            for (int r = 0; r < RPT; ++r) {
                fma2(acc[r][12], qp[r].x, qp[r].x);
                fma2(acc[r][12], qp[r].y, qp[r].y);
            }
        }
        // issue into buffer (tile+2)%3 == (tile-1)%3: its readers all
        // passed the sync at the top of THIS iteration.
        if (tile + 2 < NT) issueTile(tile + 2, (tile + 2) % 3);
    }

#pragma unroll
    for (int r = 0; r < RPT; ++r) {
        int gr = r0 + t + TPB * r;
        if (gr >= NQ) break;                  // last-block guard
        float s[13];
#pragma unroll
        for (int j = 0; j < 13; ++j) s[j] = pair_sum(acc[r][j]);
        float rinv = 1.0f / fmaxf(sqrtf(s[12]), 1e-12f);
#pragma unroll
        for (int n = 0; n < NPART; ++n)
            out[((size_t)(b * NPART + n)) * NQ + gr] = s[n] * rinv;
    }
}

// ---------------------------------------------------------------------------
// pred_logits[b,c] = sum_n logits[b,n,c*12+n]
// ---------------------------------------------------------------------------
__global__ void pred_kernel(float* __restrict__ out) {
    int t = blockIdx.x * blockDim.x + threadIdx.x;   // 0..25599
    if (t >= Bsz * NCLS) return;
    int b = t / NCLS, c = t % NCLS;
    float s = 0.0f;
#pragma unroll
    for (int n = 0; n < NPART; ++n)
        s += out[((size_t)(b * NPART + n)) * NQ + c * NPART + n];
    out[LOGITS_ELEMS + t] = s;
}

// ---------------------------------------------------------------------------
extern "C" void kernel_launch(void* const* d_in, const int* in_sizes, int n_in,
                              void* d_out, int out_size) {
    const float* image = (const float*)d_in[0];
    const float* query = (const float*)d_in[1];
    const int* topk = (const int*)d_in[2];
    const float* W1 = (const float*)d_in[3];
    const float* b1 = (const float*)d_in[4];
    const float* W2 = (const float*)d_in[5];
    const float* b2 = (const float*)d_in[6];
    const float* W3 = (const float*)d_in[7];
    const float* b3 = (const float*)d_in[8];
    float* out = (float*)d_out;

    float* h1; float* h2; float* img;
    cudaGetSymbolAddress((void**)&h1, g_h1);
    cudaGetSymbolAddress((void**)&h2, g_h2);
    cudaGetSymbolAddress((void**)&img, g_img);

    const int LOGITS_SMEM = 73728;   // 48KB q (3 buf) + 24KB img
    cudaFuncSetAttribute(logits_kernel,
                         cudaFuncAttributeMaxDynamicSharedMemorySize,
                         LOGITS_SMEM);

    // launch order keeps logits at global index 5 (2 harness preamble
    // launches + 3 here) so ncu -s 5 -c 1 captures it.
    gemm_kernel<true ><<<dim3(MROWS / GBM, DV / GBN), 256>>>(image, W1, b1, h1, DV, topk);
    gemm_kernel<false><<<dim3(MROWS / GBM, DV / GBN), 256>>>(h1, W2, b2, h2, DV, nullptr);
    gemm_kernel<false><<<dim3(MROWS / GBM, DT / GBN), 256>>>(h2, W3, b3, img, DT, nullptr);
    logits_kernel<<<dim3((NQ + RPB - 1) / RPB, Bsz), TPB, LOGITS_SMEM>>>(query, out);
    pred_kernel<<<(Bsz * NCLS + 255) / 256, 256>>>(out);
}

// round 12
// speedup vs baseline: 1.3462x; 1.0877x over previous
#include <cuda_runtime.h>
#include <math.h>

// ---------------------------------------------------------------------------
// OwlViT prediction head
//   B=32, P=576, DV=768, DT=512, N_PARTS=12, K=3, NUM_CLASSES=800
//   out = [logits_reshaped (384*9600) | pred_logits (32*800)] fp32
// ---------------------------------------------------------------------------

#define Bsz 32
#define Pn 576
#define DV 768
#define DT 512
#define NPART 12
#define TOPK 3
#define NCLS 800
#define NQ (NCLS * NPART)      // 9600 query rows per batch
#define MROWS (Bsz * NPART)    // 384
#define LOGITS_ELEMS ((size_t)MROWS * NQ)

// scratch (static device memory; no allocations allowed)
__device__ float g_h1[MROWS * DV];
__device__ float g_h2[MROWS * DV];
__device__ float g_img[MROWS * DT];

// ---------------------------------------------------------------------------
__device__ __forceinline__ void fma2(unsigned long long& d,
                                     unsigned long long a,
                                     unsigned long long b) {
    asm("fma.rn.f32x2 %0, %1, %2, %0;" : "+l"(d) : "l"(a), "l"(b));
}

__device__ __forceinline__ float pair_sum(unsigned long long v) {
    float lo = __uint_as_float((unsigned)(v & 0xffffffffull));
    float hi = __uint_as_float((unsigned)(v >> 32));
    return lo + hi;
}

__device__ __forceinline__ float gelu_exact(float x) {
    return 0.5f * x * (1.0f + erff(x * 0.70710678118654752f));
}

__device__ __forceinline__ void cp_async16(unsigned dst, const void* src) {
    asm volatile("cp.async.cg.shared.global [%0], [%1], 16;"
                 :: "r"(dst), "l"(src));
}
__device__ __forceinline__ void cp_commit() {
    asm volatile("cp.async.commit_group;");
}
__device__ __forceinline__ void cp_wait1() {
    asm volatile("cp.async.wait_group 1;");
}
__device__ __forceinline__ void cp_wait0() {
    asm volatile("cp.async.wait_group 0;");
}

// ---------------------------------------------------------------------------
// GEMM: C[M,N] = gelu(A[M,768] * W[N,768]^T + bias), smem double-buffered.
// BM=32 BN=64 BK=32, 256 threads, 2x4 outputs/thread, f32x2 k-pair FMAs.
// GATHER=true: A row r is the dedup-sum of topk image rows (fused gather).
// ---------------------------------------------------------------------------
#define GBM 32
#define GBN 64
#define GBK 32
#define GPAD 36
#define NITER (DV / GBK)   // 24

template<bool GATHER>
__global__ void __launch_bounds__(256)
gemm_kernel(const float* __restrict__ A, const float* __restrict__ W,
            const float* __restrict__ bias, float* __restrict__ C, int N,
            const int* __restrict__ idx) {
    __shared__ __align__(16) float As[2][GBM][GPAD];
    __shared__ __align__(16) float Ws[2][GBN][GPAD];
    int t = threadIdx.x;
    int tx = t & 15;                 // cols tx + 16j
    int ty = t >> 4;                 // rows ty*2 + i
    int bm = blockIdx.x * GBM, bn = blockIdx.y * GBN;

    int ar = t >> 3, ak = (t & 7) * 4;    // A tile: 1 float4/thread
    int wr = t >> 2, wk = (t & 3) * 8;    // W tile: 2 float4/thread

    const float *Arow0, *Arow1, *Arow2;
    bool u1 = false, u2 = false;
    if (GATHER) {
        int row = bm + ar;
        int bb = row / NPART, n = row - bb * NPART;
        int i0 = idx[(bb * TOPK + 0) * NPART + n];
        int i1 = idx[(bb * TOPK + 1) * NPART + n];
        int i2 = idx[(bb * TOPK + 2) * NPART + n];
        i0 = min(max(i0, 0), Pn - 1);
        i1 = min(max(i1, 0), Pn - 1);
        i2 = min(max(i2, 0), Pn - 1);
        u1 = (i1 != i0);
        u2 = (i2 != i0) && (i2 != i1);
        const float* base = A + (size_t)bb * Pn * DV;
        Arow0 = base + (size_t)i0 * DV;
        Arow1 = base + (size_t)i1 * DV;
        Arow2 = base + (size_t)i2 * DV;
    } else {
        Arow0 = A + (size_t)(bm + ar) * DV;
        Arow1 = Arow0; Arow2 = Arow0;
    }
    const float* Wg = W + (size_t)(bn + wr) * DV;

    auto loadA = [&](int k0) -> float4 {
        float4 s = *(const float4*)(Arow0 + k0 + ak);
        if (GATHER) {
            if (u1) { float4 v = *(const float4*)(Arow1 + k0 + ak);
                      s.x += v.x; s.y += v.y; s.z += v.z; s.w += v.w; }
            if (u2) { float4 v = *(const float4*)(Arow2 + k0 + ak);
                      s.x += v.x; s.y += v.y; s.z += v.z; s.w += v.w; }
        }
        return s;
    };

    unsigned long long acc2[2][4];
#pragma unroll
    for (int i = 0; i < 2; ++i)
#pragma unroll
        for (int j = 0; j < 4; ++j) acc2[i][j] = 0ull;

    // prologue: tile0 -> smem[0]; tile1 -> regs
    float4 a_r = loadA(0);
    float4 w_r0 = *(const float4*)(Wg + wk);
    float4 w_r1 = *(const float4*)(Wg + wk + 4);
    *(float4*)&As[0][ar][ak] = a_r;
    *(float4*)&Ws[0][wr][wk] = w_r0;
    *(float4*)&Ws[0][wr][wk + 4] = w_r1;
    a_r  = loadA(GBK);
    w_r0 = *(const float4*)(Wg + GBK + wk);
    w_r1 = *(const float4*)(Wg + GBK + wk + 4);
    __syncthreads();

#pragma unroll 1
    for (int i = 0; i < NITER; ++i) {
        int buf = i & 1, nbuf = buf ^ 1;
        if (i + 1 < NITER) {
            *(float4*)&As[nbuf][ar][ak] = a_r;
            *(float4*)&Ws[nbuf][wr][wk] = w_r0;
            *(float4*)&Ws[nbuf][wr][wk + 4] = w_r1;
        }
        if (i + 2 < NITER) {
            int k0 = (i + 2) * GBK;
            a_r  = loadA(k0);
            w_r0 = *(const float4*)(Wg + k0 + wk);
            w_r1 = *(const float4*)(Wg + k0 + wk + 4);
        }
#pragma unroll
        for (int kk = 0; kk < GBK; kk += 4) {
            ulonglong2 ap[2], wp[4];
            ap[0] = *(const ulonglong2*)&As[buf][ty * 2][kk];
            ap[1] = *(const ulonglong2*)&As[buf][ty * 2 + 1][kk];
#pragma unroll
            for (int j = 0; j < 4; ++j)
                wp[j] = *(const ulonglong2*)&Ws[buf][tx + 16 * j][kk];
#pragma unroll
            for (int ii = 0; ii < 2; ++ii)
#pragma unroll
                for (int j = 0; j < 4; ++j) {
                    fma2(acc2[ii][j], ap[ii].x, wp[j].x);
                    fma2(acc2[ii][j], ap[ii].y, wp[j].y);
                }
        }
        __syncthreads();
    }

#pragma unroll
    for (int i = 0; i < 2; ++i) {
        int row = bm + ty * 2 + i;
#pragma unroll
        for (int j = 0; j < 4; ++j) {
            int col = bn + tx + 16 * j;
            float x = pair_sum(acc2[i][j]) + bias[col];
            C[(size_t)row * N + col] = gelu_exact(x);
        }
    }
}

// ---------------------------------------------------------------------------
// logits: lane-owns-row, 2 rows/thread, cp.async 3-stage pipeline.
// Block = 128 threads owning rows {t, t+128} of a 256-row stripe.
// q tiles 256 rows x 8 k (8KB), 3 buffers. Staging: 4 cp.async/thread with
// PERSISTENT incremental source pointers (+32B per tile) and precomputed
// 32-bit dst offsets -> minimal address registers (R11's 148-reg defect).
// smem layout [buf][slot][row] float4, slot1 rotated +4 rows: LDGSTS store
// phase and LDS read phase both bank-conflict-free.
// One __syncthreads per tile; wait_group(1) normally, wait_group(0) on the
// FINAL tile (only 1 group pending there - the R10 bug, kept fixed).
// Dynamic smem: q 3x8KB + img 24KB = 48KB -> 4 blocks/SM (16 warps).
// ---------------------------------------------------------------------------
#define QT 8
#define NT (DT / QT)     // 64 tiles
#define RPT 2
#define TPB 128
#define RPB 256          // grid.x = ceil(9600/256) = 38 (last block guarded)
#define QBUF (RPB * 2)   // float4s per buffer (2 slots x 256 rows) = 8KB

__global__ void __launch_bounds__(TPB, 4)
logits_kernel(const float* __restrict__ q, float* __restrict__ out) {
    extern __shared__ __align__(16) float smem[];
    float4* q_s  = (float4*)smem;          // [3][2][256] float4 = 24KB
    float* img_s = smem + 6144;            // 12*512 floats = 24KB

    int t = threadIdx.x;
    int warp = t >> 5, lane = t & 31;
    int b = blockIdx.y;
    int r0 = blockIdx.x * RPB;

    const float* qB = q + (size_t)b * NQ * DT;

    // --- staging setup: 4 float4/thread/tile ---
    // idx = j*128 + t -> row = idx>>1 (2 lanes per row), slot = idx&1.
    // Persistent source pointers, advanced +QT floats per issued tile.
    const float* srcp[4];
    unsigned dst0[4];                      // dst smem addr for buf 0
#pragma unroll
    for (int j = 0; j < 4; ++j) {
        int idx = j * TPB + t;
        int row = idx >> 1, slot = idx & 1;
        int rg = r0 + row; if (rg > NQ - 1) rg = NQ - 1;   // last-block clamp
        srcp[j] = qB + (size_t)rg * DT + slot * 4;
        int rr = (row + 4 * slot) & (RPB - 1);             // rotation: slot1 +4
        dst0[j] = (unsigned)__cvta_generic_to_shared(
            &q_s[slot * RPB + rr]);
    }

    auto issueTile = [&](int buf) {
        unsigned boff = (unsigned)buf * (QBUF * 16);       // bytes per buffer
#pragma unroll
        for (int j = 0; j < 4; ++j) {
            cp_async16(dst0[j] + boff, srcp[j]);
            srcp[j] += QT;
        }
        cp_commit();
    };

    // start the pipeline before img staging
    issueTile(0);
    issueTile(1);

    {   // stage img tile for this batch (1536 float4, 12/thread)
        const float4* src = (const float4*)(g_img + (size_t)b * NPART * DT);
        float4* dst = (float4*)img_s;
#pragma unroll
        for (int i = 0; i < 12; ++i)
            dst[t + i * TPB] = src[t + i * TPB];
    }
    __syncthreads();

    // fused l2 normalization of the 12 img rows (4 warps, 3 rows each)
    for (int row = warp; row < NPART; row += 4) {
        float* rp = img_s + row * DT;
        float4 v0 = *(float4*)(rp + lane * 4);
        float4 v1 = *(float4*)(rp + lane * 4 + 128);
        float4 v2 = *(float4*)(rp + lane * 4 + 256);
        float4 v3 = *(float4*)(rp + lane * 4 + 384);
        float ss = v0.x*v0.x + v0.y*v0.y + v0.z*v0.z + v0.w*v0.w
                 + v1.x*v1.x + v1.y*v1.y + v1.z*v1.z + v1.w*v1.w
                 + v2.x*v2.x + v2.y*v2.y + v2.z*v2.z + v2.w*v2.w
                 + v3.x*v3.x + v3.y*v3.y + v3.z*v3.z + v3.w*v3.w;
#pragma unroll
        for (int off = 16; off > 0; off >>= 1)
            ss += __shfl_xor_sync(0xffffffffu, ss, off);
        float rinv = 1.0f / fmaxf(sqrtf(ss), 1e-12f);
        v0.x*=rinv; v0.y*=rinv; v0.z*=rinv; v0.w*=rinv;
        v1.x*=rinv; v1.y*=rinv; v1.z*=rinv; v1.w*=rinv;
        v2.x*=rinv; v2.y*=rinv; v2.z*=rinv; v2.w*=rinv;
        v3.x*=rinv; v3.y*=rinv; v3.z*=rinv; v3.w*=rinv;
        *(float4*)(rp + lane * 4)       = v0;
        *(float4*)(rp + lane * 4 + 128) = v1;
        *(float4*)(rp + lane * 4 + 256) = v2;
        *(float4*)(rp + lane * 4 + 384) = v3;
    }
    // img-norm visibility to all warps is covered by the first in-loop
    // __syncthreads below (before any compute reads img_s).

    unsigned long long acc[RPT][13];
#pragma unroll
    for (int r = 0; r < RPT; ++r)
#pragma unroll
        for (int j = 0; j < 13; ++j) acc[r][j] = 0ull;

    int bufc = 0;                          // buffer of current tile (mod 3)
#pragma unroll 1
    for (int tile = 0; tile < NT; ++tile) {
        // pending groups: {tile, tile+1} normally -> wait_group(1) drains
        // group 'tile'. On the LAST tile only {tile} pends -> drain all.
        if (tile + 1 < NT) cp_wait1(); else cp_wait0();
        __syncthreads();             // all threads' copies + img norm visible

        const float4* qbuf = q_s + bufc * QBUF;
#pragma unroll
        for (int c = 0; c < 2; ++c) {
            int k = tile * QT + c * 4;
            ulonglong2 qp[RPT];
#pragma unroll
            for (int r = 0; r < RPT; ++r) {
                int rr = (t + TPB * r + 4 * c) & (RPB - 1);
                qp[r] = *(const ulonglong2*)&qbuf[c * RPB + rr];
            }
#pragma unroll
            for (int n = 0; n < NPART; ++n) {
                ulonglong2 im = *(const ulonglong2*)&img_s[n * DT + k];
#pragma unroll
                for (int r = 0; r < RPT; ++r) {
                    fma2(acc[r][n], qp[r].x, im.x);
                    fma2(acc[r][n], qp[r].y, im.y);
                }
            }
#pragma unroll
            for (int r = 0; r < RPT; ++r) {
                fma2(acc[r][12], qp[r].x, qp[r].x);
                fma2(acc[r][12], qp[r].y, qp[r].y);
            }
        }
        // issue into buffer (tile+2)%3 == (tile-1)%3: its readers all
        // passed the sync at the top of THIS iteration.
        int nbuf = bufc + 2; if (nbuf >= 3) nbuf -= 3;
        if (tile + 2 < NT) issueTile(nbuf);
        if (++bufc == 3) bufc = 0;
    }

#pragma unroll
    for (int r = 0; r < RPT; ++r) {
        int gr = r0 + t + TPB * r;
        if (gr >= NQ) break;                  // last-block guard
        float s[13];
#pragma unroll
        for (int j = 0; j < 13; ++j) s[j] = pair_sum(acc[r][j]);
        float rinv = 1.0f / fmaxf(sqrtf(s[12]), 1e-12f);
#pragma unroll
        for (int n = 0; n < NPART; ++n)
            out[((size_t)(b * NPART + n)) * NQ + gr] = s[n] * rinv;
    }
}

// ---------------------------------------------------------------------------
// pred_logits[b,c] = sum_n logits[b,n,c*12+n]
// ---------------------------------------------------------------------------
__global__ void pred_kernel(float* __restrict__ out) {
    int t = blockIdx.x * blockDim.x + threadIdx.x;   // 0..25599
    if (t >= Bsz * NCLS) return;
    int b = t / NCLS, c = t % NCLS;
    float s = 0.0f;
#pragma unroll
    for (int n = 0; n < NPART; ++n)
        s += out[((size_t)(b * NPART + n)) * NQ + c * NPART + n];
    out[LOGITS_ELEMS + t] = s;
}

// ---------------------------------------------------------------------------
extern "C" void kernel_launch(void* const* d_in, const int* in_sizes, int n_in,
                              void* d_out, int out_size) {
    const float* image = (const float*)d_in[0];
    const float* query = (const float*)d_in[1];
    const int* topk = (const int*)d_in[2];
    const float* W1 = (const float*)d_in[3];
    const float* b1 = (const float*)d_in[4];
    const float* W2 = (const float*)d_in[5];
    const float* b2 = (const float*)d_in[6];
    const float* W3 = (const float*)d_in[7];
    const float* b3 = (const float*)d_in[8];
    float* out = (float*)d_out;

    float* h1; float* h2; float* img;
    cudaGetSymbolAddress((void**)&h1, g_h1);
    cudaGetSymbolAddress((void**)&h2, g_h2);
    cudaGetSymbolAddress((void**)&img, g_img);

    const int LOGITS_SMEM = 49152;   // 24KB q (3 buf) + 24KB img
    cudaFuncSetAttribute(logits_kernel,
                         cudaFuncAttributeMaxDynamicSharedMemorySize,
                         LOGITS_SMEM);

    // launch order keeps logits at global index 5 (2 harness preamble
    // launches + 3 here) so ncu -s 5 -c 1 captures it.
    gemm_kernel<true ><<<dim3(MROWS / GBM, DV / GBN), 256>>>(image, W1, b1, h1, DV, topk);
    gemm_kernel<false><<<dim3(MROWS / GBM, DV / GBN), 256>>>(h1, W2, b2, h2, DV, nullptr);
    gemm_kernel<false><<<dim3(MROWS / GBM, DT / GBN), 256>>>(h2, W3, b3, img, DT, nullptr);
    logits_kernel<<<dim3((NQ + RPB - 1) / RPB, Bsz), TPB, LOGITS_SMEM>>>(query, out);
    pred_kernel<<<(Bsz * NCLS + 255) / 256, 256>>>(out);
}